// round 12
// baseline (speedup 1.0000x reference)
#include <cuda_runtime.h>
#include <math.h>

#define Bb 16
#define II 512
#define HH 1024
#define BH (Bb*HH)            // 16384
#define NJT 64

// Output offsets (floats): h, c, e_w_ix, e_w_ih, e_b_i, e_w_fx, e_w_fh, e_b_f, e_w_cx, e_w_ch, e_b_c
#define OFF_H     0
#define OFF_C     16384
#define OFF_EWIX  32768
#define OFF_EWIH  8421376
#define OFF_EBI   25198592
#define OFF_EWFX  25214976
#define OFF_EWFH  33603584
#define OFF_EBF   50380800
#define OFF_EWCX  50397184
#define OFF_EWCH  58785792
#define OFF_EBC   75563008

// Scratch (no allocation allowed)
__device__ float g_pre[4 * BH];   // accumulated pre-activations (atomicAdd)
__device__ int   g_cnt[NJT];      // block arrivals per j-tile (16 = ready)

struct GatePtrs {
    const float* wx[4];
    const float* wh[4];
};

#define FMA4(A, Z, ACC)                         \
    ACC = fmaf((A).x, (Z).x, ACC);              \
    ACC = fmaf((A).y, (Z).y, ACC);              \
    ACC = fmaf((A).z, (Z).z, ACC);              \
    ACC = fmaf((A).w, (Z).w, ACC);

__global__ void reset_kernel() {
    const int idx = blockIdx.x * 256 + threadIdx.x;
    if (idx < 4 * BH) g_pre[idx] = 0.f;
    if (blockIdx.x == 0 && threadIdx.x < NJT) g_cnt[threadIdx.x] = 0;
}

// ---------------------------------------------------------------------------
// ONE homogeneous kernel. grid = (16, 64): blockIdx.y = jt (16 j-rows),
// blockIdx.x = bs (batch for streaming AND gate-slice index).
// Phase 1: warps 0-5 run one gate warp-task each (2 j-rows x 16 batches x
//          512 cols; the 96 tasks per jt partition 16j x 4g x 1536k), then
//          atomicAdd results into g_pre. Each weight element is read once.
// Phase 2: arrive/spin on g_cnt[jt] (15 siblings doing identical work).
// Phase 3: pointwise coefficients for (jt, bs) + h/c/e_b outputs.
// Phase 4: stream the trace tile (proven 5.9 TB/s structure, unchanged).
// ---------------------------------------------------------------------------
#define JT 16

__global__ __launch_bounds__(256, 4) void fused_kernel(
    const float* __restrict__ x, const float* __restrict__ h_last,
    const float* __restrict__ c_last, GatePtrs p,
    const float* __restrict__ b_i, const float* __restrict__ b_f,
    const float* __restrict__ b_o, const float* __restrict__ b_c,
    const float* __restrict__ eb_i, const float* __restrict__ eb_f,
    const float* __restrict__ eb_c,
    const float* __restrict__ e_ix, const float* __restrict__ e_ih,
    const float* __restrict__ e_fx, const float* __restrict__ e_fh,
    const float* __restrict__ e_cx, const float* __restrict__ e_ch,
    float* __restrict__ out)
{
    __shared__ float4 scf[JT];

    const int tid  = threadIdx.x;
    const int warp = tid >> 5;
    const int lane = tid & 31;
    const int jt   = blockIdx.y;
    const int bs   = blockIdx.x;          // batch index AND slice index
    const int j0t  = jt * 16;

    // ---------------- Phase 1: gate warp-task (warps 0-5) ----------------
    if (warp < 6) {
        const int task = bs * 6 + warp;   // 0..95 within this jt
        const int pair = task & 7;        // which 2-row pair of the 16
        const int g    = (task >> 3) & 3; // gate
        const int kcs  = task >> 5;       // 0: x[0:512], 1: h[0:512], 2: h[512:1024]

        const float* wbase = (kcs == 0) ? p.wx[g] : p.wh[g];
        const int rowlen   = (kcs == 0) ? II : HH;
        const int koff     = (kcs == 2) ? 512 : 0;
        const float4* zsrc = (kcs == 0) ? (const float4*)x : (const float4*)h_last;
        const int rowf4    = (kcs == 0) ? (II / 4) : (HH / 4);
        const int zoff     = (kcs == 2) ? 128 : 0;

        const int j0 = j0t + pair * 2;
        const float4* w0 = (const float4*)(wbase + (size_t)j0 * rowlen + koff);
        const float4* w1 = (const float4*)(wbase + (size_t)(j0 + 1) * rowlen + koff);

        float a[32];
#pragma unroll
        for (int m = 0; m < 32; m++) a[m] = 0.f;

#pragma unroll
        for (int it = 0; it < 4; it++) {
            float4 A0 = w0[it * 32 + lane];
            float4 A1 = w1[it * 32 + lane];
            const int k4 = zoff + it * 32 + lane;
#pragma unroll
            for (int b2 = 0; b2 < Bb; b2++) {
                float4 z = __ldg(zsrc + b2 * rowf4 + k4);
                FMA4(A0, z, a[b2]);
                FMA4(A1, z, a[16 + b2]);
            }
        }

        // 32-value butterfly reduction (31 shuffles)
#pragma unroll
        for (int k = 0; k < 5; k++) {
            const int d = 1 << k;
            const int n = 32 >> k;
            const bool hi = (lane >> k) & 1;
#pragma unroll
            for (int m = 0; m < 16; m++) {
                if (m < n / 2) {
                    float mine = hi ? a[m] : a[m + n / 2];
                    float got  = __shfl_xor_sync(0xffffffffu, mine, d);
                    a[m] = (hi ? a[m + n / 2] : a[m]) + got;
                }
            }
        }

        const unsigned rev = __brev((unsigned)lane) >> 27;  // v = jj*16 + b
        const int jj = rev >> 4;
        const int b2 = rev & 15;
        atomicAdd(&g_pre[g * BH + b2 * HH + j0 + jj], a[0]);
    }
    __syncthreads();

    // ---------------- Phase 2: arrive + wait for siblings ----------------
    if (tid == 0) {
        __threadfence();
        atomicAdd(&g_cnt[jt], 1);
        while (atomicAdd(&g_cnt[jt], 0) < 16) __nanosleep(64);
        __threadfence();
    }
    __syncthreads();

    // ---------------- Phase 3: pointwise for (jt, bs) --------------------
    const int b = bs;
    if (tid < JT) {
        const int j   = j0t + tid;
        const int idx = b * HH + j;

        float pi = b_i[j] + g_pre[0 * BH + idx];
        float pf = b_f[j] + g_pre[1 * BH + idx];
        float po = b_o[j] + g_pre[2 * BH + idx];
        float pc = b_c[j] + g_pre[3 * BH + idx];

        float i  = 1.f / (1.f + expf(-pi));
        float f  = 1.f / (1.f + expf(-pf));
        float o  = 1.f / (1.f + expf(-po));
        float ch = tanhf(pc);
        float cl = c_last[idx];

        float c = fmaf(f, cl, i * ch);
        float h = o * c;
        float di  = i * (1.f - i);
        float df  = f * (1.f - f);
        float dch = 1.f - ch * ch;
        float ai = di * ch;
        float af = df * cl;
        float ac = dch * i;

        out[OFF_H + idx]   = h;
        out[OFF_C + idx]   = c;
        out[OFF_EBI + idx] = fmaf(eb_i[idx], f, ai);
        out[OFF_EBF + idx] = fmaf(eb_f[idx], f, af);
        out[OFF_EBC + idx] = fmaf(eb_c[idx], f, ac);
        scf[tid] = make_float4(f, ai, af, ac);
    }
    __syncthreads();

    // ---------------- Phase 4: trace streaming (proven structure) --------
    const int j0 = j0t;
    const size_t baseH = (size_t)(b * HH + j0) * (HH / 4);
    const size_t baseI = (size_t)(b * HH + j0) * (II / 4);

    const float4 hv = __ldg((const float4*)(h_last + b * HH) + tid);
    const float4 xv = __ldg((const float4*)(x + b * II) + (tid & 127));
    const int xsel = tid >> 7;

#define TRACE_H(SRC, OFF, SEL)                                              \
    {                                                                       \
        const float4* ein = (const float4*)(SRC) + baseH;                   \
        float4* eo = (float4*)(out + (OFF)) + baseH;                        \
        _Pragma("unroll")                                                   \
        for (int it = 0; it < JT; it++) {                                   \
            const int t = tid + it * 256;                                   \
            float4 cf = scf[it];                                            \
            float fv = cf.x, aa = cf.SEL;                                   \
            float4 e  = __ldcs(ein + t);                                    \
            float4 rr;                                                      \
            rr.x = fmaf(e.x, fv, aa * hv.x);                                \
            rr.y = fmaf(e.y, fv, aa * hv.y);                                \
            rr.z = fmaf(e.z, fv, aa * hv.z);                                \
            rr.w = fmaf(e.w, fv, aa * hv.w);                                \
            __stcs(eo + t, rr);                                             \
        }                                                                   \
    }

#define TRACE_X(SRC, OFF, SEL)                                              \
    {                                                                       \
        const float4* ein = (const float4*)(SRC) + baseI;                   \
        float4* eo = (float4*)(out + (OFF)) + baseI;                        \
        _Pragma("unroll")                                                   \
        for (int it = 0; it < JT / 2; it++) {                               \
            const int t = tid + it * 256;                                   \
            float4 cf = scf[it * 2 + xsel];                                 \
            float fv = cf.x, aa = cf.SEL;                                   \
            float4 e  = __ldcs(ein + t);                                    \
            float4 rr;                                                      \
            rr.x = fmaf(e.x, fv, aa * xv.x);                                \
            rr.y = fmaf(e.y, fv, aa * xv.y);                                \
            rr.z = fmaf(e.z, fv, aa * xv.z);                                \
            rr.w = fmaf(e.w, fv, aa * xv.w);                                \
            __stcs(eo + t, rr);                                             \
        }                                                                   \
    }

    TRACE_H(e_ih, OFF_EWIH, y)
    TRACE_H(e_fh, OFF_EWFH, z)
    TRACE_H(e_ch, OFF_EWCH, w)
    TRACE_X(e_ix, OFF_EWIX, y)
    TRACE_X(e_fx, OFF_EWFX, z)
    TRACE_X(e_cx, OFF_EWCX, w)
}

// ---------------------------------------------------------------------------
extern "C" void kernel_launch(void* const* d_in, const int* in_sizes, int n_in,
                              void* d_out, int out_size)
{
    const float* x      = (const float*)d_in[0];
    const float* w_ix   = (const float*)d_in[1];
    const float* w_ih   = (const float*)d_in[2];
    const float* b_i    = (const float*)d_in[3];
    const float* w_fx   = (const float*)d_in[4];
    const float* w_fh   = (const float*)d_in[5];
    const float* b_f    = (const float*)d_in[6];
    const float* w_ox   = (const float*)d_in[7];
    const float* w_oh   = (const float*)d_in[8];
    const float* b_o    = (const float*)d_in[9];
    const float* w_cx   = (const float*)d_in[10];
    const float* w_ch   = (const float*)d_in[11];
    const float* b_c    = (const float*)d_in[12];
    const float* h_last = (const float*)d_in[13];
    const float* c_last = (const float*)d_in[14];
    const float* e_w_ix = (const float*)d_in[15];
    const float* e_w_ih = (const float*)d_in[16];
    const float* e_b_i  = (const float*)d_in[17];
    const float* e_w_fx = (const float*)d_in[18];
    const float* e_w_fh = (const float*)d_in[19];
    const float* e_b_f  = (const float*)d_in[20];
    const float* e_w_cx = (const float*)d_in[21];
    const float* e_w_ch = (const float*)d_in[22];
    const float* e_b_c  = (const float*)d_in[23];
    float* out = (float*)d_out;

    GatePtrs p;
    p.wx[0] = w_ix; p.wx[1] = w_fx; p.wx[2] = w_ox; p.wx[3] = w_cx;
    p.wh[0] = w_ih; p.wh[1] = w_fh; p.wh[2] = w_oh; p.wh[3] = w_ch;

    reset_kernel<<<(4 * BH + 255) / 256, 256>>>();

    dim3 grid(Bb, NJT);   // bs fast, jt slow -> 16 siblings bid-contiguous
    fused_kernel<<<grid, 256>>>(x, h_last, c_last, p,
                                b_i, b_f, b_o, b_c,
                                e_b_i, e_b_f, e_b_c,
                                e_w_ix, e_w_ih, e_w_fx, e_w_fh,
                                e_w_cx, e_w_ch, out);
}

// round 13
// speedup vs baseline: 1.2742x; 1.2742x over previous
#include <cuda_runtime.h>
#include <math.h>

#define Bb 16
#define II 512
#define HH 1024
#define BH (Bb*HH)            // 16384
#define NKC 6                 // K-chunks of 256 columns

// Output offsets (floats): h, c, e_w_ix, e_w_ih, e_b_i, e_w_fx, e_w_fh, e_b_f, e_w_cx, e_w_ch, e_b_c
#define OFF_H     0
#define OFF_C     16384
#define OFF_EWIX  32768
#define OFF_EWIH  8421376
#define OFF_EBI   25198592
#define OFF_EWFX  25214976
#define OFF_EWFH  33603584
#define OFF_EBF   50380800
#define OFF_EWCX  50397184
#define OFF_EWCH  58785792
#define OFF_EBC   75563008

// Scratch (no allocation allowed).
// Layout: g_part[kc][g][j*16 + b]  (b contiguous -> coalesced stores)
__device__ float g_part[NKC][4][HH * Bb];

struct GatePtrs {
    const float* wx[4];
    const float* wh[4];
};

typedef unsigned long long u64;

__device__ __forceinline__ u64 pack2(float lo, float hi) {
    u64 r;
    asm("mov.b64 %0, {%1, %2};" : "=l"(r) : "f"(lo), "f"(hi));
    return r;
}
__device__ __forceinline__ void fma2(u64& acc, u64 a, u64 b) {
    asm("fma.rn.f32x2 %0, %1, %2, %0;" : "+l"(acc) : "l"(a), "l"(b));
}
__device__ __forceinline__ void unpack2(u64 v, float& lo, float& hi) {
    asm("mov.b64 {%0, %1}, %2;" : "=f"(lo), "=f"(hi) : "l"(v));
}

__global__ void noop_kernel() {}

// ---------------------------------------------------------------------------
// Kernel 1: gate pre-activation partials with packed f32x2 FMA (R11 math).
// grid = (HH/16, 4 gates, 6 K-chunks of 256 cols), block = 128 (4 warps).
// Each warp: 4 j-rows x 16 batches; batches paired into f32x2 lanes.
// Stores: one float2 per lane -> 4 x 64B contiguous segments per warp.
// ---------------------------------------------------------------------------
__global__ __launch_bounds__(128, 4) void gates_kernel(
    const float* __restrict__ x, const float* __restrict__ h_last, GatePtrs p)
{
    const int tid  = threadIdx.x;
    const int warp = tid >> 5;
    const int lane = tid & 31;
    const int kc   = blockIdx.z;
    const int g    = blockIdx.y;
    const int j0   = blockIdx.x * 16 + warp * 4;

    const float* wbase = (kc < 2) ? p.wx[g] : p.wh[g];
    const int rowlen   = (kc < 2) ? II : HH;
    const int koff     = (kc < 2) ? kc * 256 : (kc - 2) * 256;

    const float4* zsrc = (kc < 2) ? (const float4*)x : (const float4*)h_last;
    const int rowf4    = (kc < 2) ? (II / 4) : (HH / 4);
    const int zoff     = (kc < 2) ? kc * 64 : (kc - 2) * 64;

    // acc[r*8+bp] accumulates batches (2bp, 2bp+1) for row j0+r
    u64 acc[32];
#pragma unroll
    for (int m = 0; m < 32; m++) acc[m] = 0ull;

#pragma unroll
    for (int it = 0; it < 2; it++) {
        float4 wr[4];
#pragma unroll
        for (int r = 0; r < 4; r++)
            wr[r] = *((const float4*)(wbase + (size_t)(j0 + r) * rowlen + koff)
                      + it * 32 + lane);

        u64 w2[4][4];
#pragma unroll
        for (int r = 0; r < 4; r++) {
            w2[r][0] = pack2(wr[r].x, wr[r].x);
            w2[r][1] = pack2(wr[r].y, wr[r].y);
            w2[r][2] = pack2(wr[r].z, wr[r].z);
            w2[r][3] = pack2(wr[r].w, wr[r].w);
        }

        const int k4 = zoff + it * 32 + lane;
#pragma unroll
        for (int bp = 0; bp < 8; bp++) {
            float4 zl = __ldg(zsrc + (2 * bp)     * rowf4 + k4);
            float4 zh = __ldg(zsrc + (2 * bp + 1) * rowf4 + k4);
            u64 z0 = pack2(zl.x, zh.x);
            u64 z1 = pack2(zl.y, zh.y);
            u64 z2 = pack2(zl.z, zh.z);
            u64 z3 = pack2(zl.w, zh.w);
#pragma unroll
            for (int r = 0; r < 4; r++) {
                fma2(acc[r * 8 + bp], w2[r][0], z0);
                fma2(acc[r * 8 + bp], w2[r][1], z1);
                fma2(acc[r * 8 + bp], w2[r][2], z2);
                fma2(acc[r * 8 + bp], w2[r][3], z3);
            }
        }
    }

    // Unpack to 64 scalars: a[r*16 + b]
    float a[64];
#pragma unroll
    for (int r = 0; r < 4; r++)
#pragma unroll
        for (int bp = 0; bp < 8; bp++)
            unpack2(acc[r * 8 + bp], a[r * 16 + 2 * bp], a[r * 16 + 2 * bp + 1]);

    // Multi-value butterfly reduction: 64 values -> 2 per lane (62 shuffles).
#pragma unroll
    for (int k = 0; k < 5; k++) {
        const int d = 1 << k;
        const int n = 64 >> k;
        const bool hi = (lane >> k) & 1;
#pragma unroll
        for (int m = 0; m < 32; m++) {
            if (m < n / 2) {
                float mine = hi ? a[m] : a[m + n / 2];
                float got  = __shfl_xor_sync(0xffffffffu, mine, d);
                a[m] = (hi ? a[m + n / 2] : a[m]) + got;
            }
        }
    }

    // lane L holds values v=(rev<<1) and v+1, i.e. b = (rev&7)*2, b+1 for
    // row jj = rev>>3. Store as ONE float2 -> coalesced 64B row segments.
    const unsigned rev = __brev((unsigned)lane) >> 27;
    const int jj = rev >> 3;
    float2* dst = (float2*)&g_part[kc][g][(j0 + jj) * Bb];
    dst[rev & 7] = make_float2(a[0], a[1]);
}

// ---------------------------------------------------------------------------
// Kernel 2: fused pointwise + HBM-bound trace update (proven 5.9 TB/s).
// ---------------------------------------------------------------------------
#define JT 16

__global__ __launch_bounds__(256) void trace_kernel(
    const float* __restrict__ x, const float* __restrict__ h_last,
    const float* __restrict__ c_last,
    const float* __restrict__ b_i, const float* __restrict__ b_f,
    const float* __restrict__ b_o, const float* __restrict__ b_c,
    const float* __restrict__ eb_i, const float* __restrict__ eb_f,
    const float* __restrict__ eb_c,
    const float* __restrict__ e_ix, const float* __restrict__ e_ih,
    const float* __restrict__ e_fx, const float* __restrict__ e_fh,
    const float* __restrict__ e_cx, const float* __restrict__ e_ch,
    float* __restrict__ out)
{
    __shared__ float4 sx[II / 4];   // 2KB
    __shared__ float4 sh[HH / 4];   // 4KB
    __shared__ float4 scf[JT];

    const int tid = threadIdx.x;
    const int b   = blockIdx.y;
    const int j0  = blockIdx.x * JT;

    if (tid < 128) sx[tid] = ((const float4*)(x + b * II))[tid];
    sh[tid] = ((const float4*)(h_last + b * HH))[tid];

    if (tid < JT) {
        const int j   = j0 + tid;
        const int idx = b * HH + j;
        const int gi  = j * Bb + b;

        float pi = b_i[j], pf = b_f[j], po = b_o[j], pc = b_c[j];
#pragma unroll
        for (int c = 0; c < NKC; c++) {
            pi += g_part[c][0][gi];
            pf += g_part[c][1][gi];
            po += g_part[c][2][gi];
            pc += g_part[c][3][gi];
        }

        float i  = 1.f / (1.f + expf(-pi));
        float f  = 1.f / (1.f + expf(-pf));
        float o  = 1.f / (1.f + expf(-po));
        float ch = tanhf(pc);
        float cl = c_last[idx];

        float c = fmaf(f, cl, i * ch);
        float h = o * c;
        float di  = i * (1.f - i);
        float df  = f * (1.f - f);
        float dch = 1.f - ch * ch;
        float ai = di * ch;
        float af = df * cl;
        float ac = dch * i;

        out[OFF_H + idx]   = h;
        out[OFF_C + idx]   = c;
        out[OFF_EBI + idx] = fmaf(eb_i[idx], f, ai);
        out[OFF_EBF + idx] = fmaf(eb_f[idx], f, af);
        out[OFF_EBC + idx] = fmaf(eb_c[idx], f, ac);
        scf[tid] = make_float4(f, ai, af, ac);
    }
    __syncthreads();

    const size_t baseH = (size_t)(b * HH + j0) * (HH / 4);
    const size_t baseI = (size_t)(b * HH + j0) * (II / 4);

    const float4 hv = sh[tid];
    const float4 xv = sx[tid & 127];
    const int xsel = tid >> 7;

#define TRACE_H(SRC, OFF, SEL)                                              \
    {                                                                       \
        const float4* ein = (const float4*)(SRC) + baseH;                   \
        float4* eo = (float4*)(out + (OFF)) + baseH;                        \
        _Pragma("unroll")                                                   \
        for (int it = 0; it < JT; it++) {                                   \
            const int t = tid + it * 256;                                   \
            float4 cf = scf[it];                                            \
            float fv = cf.x, aa = cf.SEL;                                   \
            float4 e  = __ldcs(ein + t);                                    \
            float4 rr;                                                      \
            rr.x = fmaf(e.x, fv, aa * hv.x);                                \
            rr.y = fmaf(e.y, fv, aa * hv.y);                                \
            rr.z = fmaf(e.z, fv, aa * hv.z);                                \
            rr.w = fmaf(e.w, fv, aa * hv.w);                                \
            __stcs(eo + t, rr);                                             \
        }                                                                   \
    }

#define TRACE_X(SRC, OFF, SEL)                                              \
    {                                                                       \
        const float4* ein = (const float4*)(SRC) + baseI;                   \
        float4* eo = (float4*)(out + (OFF)) + baseI;                        \
        _Pragma("unroll")                                                   \
        for (int it = 0; it < JT / 2; it++) {                               \
            const int t = tid + it * 256;                                   \
            float4 cf = scf[it * 2 + xsel];                                 \
            float fv = cf.x, aa = cf.SEL;                                   \
            float4 e  = __ldcs(ein + t);                                    \
            float4 rr;                                                      \
            rr.x = fmaf(e.x, fv, aa * xv.x);                                \
            rr.y = fmaf(e.y, fv, aa * xv.y);                                \
            rr.z = fmaf(e.z, fv, aa * xv.z);                                \
            rr.w = fmaf(e.w, fv, aa * xv.w);                                \
            __stcs(eo + t, rr);                                             \
        }                                                                   \
    }

    TRACE_H(e_ih, OFF_EWIH, y)
    TRACE_H(e_fh, OFF_EWFH, z)
    TRACE_H(e_ch, OFF_EWCH, w)
    TRACE_X(e_ix, OFF_EWIX, y)
    TRACE_X(e_fx, OFF_EWFX, z)
    TRACE_X(e_cx, OFF_EWCX, w)
}

// ---------------------------------------------------------------------------
extern "C" void kernel_launch(void* const* d_in, const int* in_sizes, int n_in,
                              void* d_out, int out_size)
{
    const float* x      = (const float*)d_in[0];
    const float* w_ix   = (const float*)d_in[1];
    const float* w_ih   = (const float*)d_in[2];
    const float* b_i    = (const float*)d_in[3];
    const float* w_fx   = (const float*)d_in[4];
    const float* w_fh   = (const float*)d_in[5];
    const float* b_f    = (const float*)d_in[6];
    const float* w_ox   = (const float*)d_in[7];
    const float* w_oh   = (const float*)d_in[8];
    const float* b_o    = (const float*)d_in[9];
    const float* w_cx   = (const float*)d_in[10];
    const float* w_ch   = (const float*)d_in[11];
    const float* b_c    = (const float*)d_in[12];
    const float* h_last = (const float*)d_in[13];
    const float* c_last = (const float*)d_in[14];
    const float* e_w_ix = (const float*)d_in[15];
    const float* e_w_ih = (const float*)d_in[16];
    const float* e_b_i  = (const float*)d_in[17];
    const float* e_w_fx = (const float*)d_in[18];
    const float* e_w_fh = (const float*)d_in[19];
    const float* e_b_f  = (const float*)d_in[20];
    const float* e_w_cx = (const float*)d_in[21];
    const float* e_w_ch = (const float*)d_in[22];
    const float* e_b_c  = (const float*)d_in[23];
    float* out = (float*)d_out;

    GatePtrs p;
    p.wx[0] = w_ix; p.wx[1] = w_fx; p.wx[2] = w_ox; p.wx[3] = w_cx;
    p.wh[0] = w_ih; p.wh[1] = w_fh; p.wh[2] = w_oh; p.wh[3] = w_ch;

    // Launch pattern [noop, gates, trace, noop]: with 4 launches per call,
    // ncu's "-s 5 -c 1" (skip 5) lands on launch idx 5 = iteration 2's
    // gates_kernel — finally giving us a gates profile.
    noop_kernel<<<1, 32>>>();

    dim3 g1(HH / 16, 4, NKC);
    gates_kernel<<<g1, 128>>>(x, h_last, p);

    dim3 g3(HH / JT, Bb);
    trace_kernel<<<g3, 256>>>(x, h_last, c_last, b_i, b_f, b_o, b_c,
                              e_b_i, e_b_f, e_b_c,
                              e_w_ix, e_w_ih, e_w_fx, e_w_fh,
                              e_w_cx, e_w_ch, out);

    noop_kernel<<<1, 32>>>();
}